// round 10
// baseline (speedup 1.0000x reference)
#include <cuda_runtime.h>
#include <cuda_bf16.h>
#include <cstdint>
#include <math.h>

#define D 4096
#define H 2
#define HD (D / H)     // 2048
#define E 8192

#define NSTAGE 6
#define ROW_F4 (D / 4)             // 1024 float4 per 16 KB row
#define ROW_BYTES (D * 4)          // 16384
#define STAGE_ROWS 2
#define STAGE_BYTES (STAGE_ROWS * ROW_BYTES)       // 32768
#define DYN_SMEM (NSTAGE * STAGE_BYTES)            // 196608 B

// Scratch (device globals — no allocations allowed). Fully overwritten every run.
__device__ float g_x[2 * D];
__device__ float g_qkv[2 * 3 * D];
__device__ float g_o[2 * D];
__device__ float g_x1[2 * D];
__device__ float g_h[2 * D];
__device__ float g_x2[2 * D];
__device__ float g_g[2 * E];

// ---------------------------------------------------------------------------
// mbarrier / bulk-async helpers
// ---------------------------------------------------------------------------
__device__ __forceinline__ uint32_t smem_u32(const void* p) {
    return (uint32_t)__cvta_generic_to_shared(p);
}
__device__ __forceinline__ void mbar_init(uint32_t addr, uint32_t count) {
    asm volatile("mbarrier.init.shared.b64 [%0], %1;" :: "r"(addr), "r"(count) : "memory");
}
__device__ __forceinline__ void mbar_expect_tx(uint32_t addr, uint32_t bytes) {
    asm volatile("mbarrier.arrive.expect_tx.shared.b64 _, [%0], %1;"
                 :: "r"(addr), "r"(bytes) : "memory");
}
__device__ __forceinline__ void mbar_wait(uint32_t addr, uint32_t parity) {
    asm volatile(
        "{\n\t.reg .pred P;\n\t"
        "WAITL_%=:\n\t"
        "mbarrier.try_wait.parity.acquire.cta.shared::cta.b64 P, [%0], %1, 0x989680;\n\t"
        "@P bra.uni DONEL_%=;\n\t"
        "bra.uni WAITL_%=;\n\t"
        "DONEL_%=:\n\t}"
        :: "r"(addr), "r"(parity) : "memory");
}
__device__ __forceinline__ void bulk_g2s(uint32_t dst_smem, const void* src, uint32_t bytes,
                                         uint32_t mbar) {
    asm volatile(
        "cp.async.bulk.shared::cta.global.mbarrier::complete_tx::bytes [%0], [%1], %2, [%3];"
        :: "r"(dst_smem), "l"(src), "r"(bytes), "r"(mbar) : "memory");
}

// ---------------------------------------------------------------------------
// Stage 0: per-task embeddings
// ---------------------------------------------------------------------------
__global__ void k_embed(const float* __restrict__ ray,
                        const float* __restrict__ w1, const float* __restrict__ b1,
                        const float* __restrict__ w2, const float* __restrict__ b2) {
    int i = blockIdx.x * blockDim.x + threadIdx.x;
    if (i < D) {
        float r0 = __ldg(ray + 0);
        float r1 = __ldg(ray + 1);
        g_x[i]     = fmaxf(r0 * w1[i] + b1[i], 0.0f);
        g_x[D + i] = fmaxf(r1 * w2[i] + b2[i], 0.0f);
    }
}

// ---------------------------------------------------------------------------
// Bulk-async 2-rows-per-stage GEMV (K = 4096).
// Persistent block (1/SM, 256 threads) owns a contiguous row span. Thread 0
// streams 32 KB stages (2 weight rows) through a 6-deep smem ring via
// cp.async.bulk + mbarrier. Warps 0-3 dot row A, warps 4-7 row B; x is held
// in registers (fixed positions across all rows), so smem traffic is weights
// only. ONE __syncthreads per iteration retires TWO rows; reduction slots are
// iteration-parity indexed to avoid a second barrier.
// ---------------------------------------------------------------------------
template <bool RELU, bool RESID>
__global__ void __launch_bounds__(256)
k_gemv_bulk2(const float* __restrict__ W,
             const float* __restrict__ b,
             const float* __restrict__ xin,     // [2][D]
             const float* __restrict__ resid,   // [2][N] or null
             float* __restrict__ out,           // [2][N]
             int N) {
    extern __shared__ float4 stg[];             // NSTAGE * 2 rows * 1024 float4
    __shared__ __align__(8) uint64_t mbar[NSTAGE];
    __shared__ float red[2][2][2][4];           // [iter&1][row A/B][seq][warp-in-group]

    const int tid  = threadIdx.x;
    const int warp = tid >> 5, lane = tid & 31;
    const int grp  = warp >> 2;                 // 0 = row A, 1 = row B
    const int wig  = warp & 3;                  // warp index within group
    const int gtid = tid & 127;                 // thread index within group

    const int per = (N + gridDim.x - 1) / gridDim.x;
    const int r0  = blockIdx.x * per;
    const int r1  = min(N, r0 + per);
    const int nrows = r1 - r0;
    if (nrows <= 0) return;
    const int niter = (nrows + 1) >> 1;

    // x cached in registers: this thread's 8 fixed float4 positions.
    float4 xa[8], xb[8];
    {
        const float4* __restrict__ x0 = reinterpret_cast<const float4*>(xin);
        const float4* __restrict__ x1 = reinterpret_cast<const float4*>(xin + D);
#pragma unroll
        for (int q = 0; q < 8; ++q) {
            const int idx = q * 128 + gtid;
            xa[q] = x0[idx];
            xb[q] = x1[idx];
        }
    }

    // Init barriers + prologue prefetch.
    if (tid == 0) {
#pragma unroll
        for (int s = 0; s < NSTAGE; ++s) mbar_init(smem_u32(&mbar[s]), 1);
        asm volatile("fence.proxy.async.shared::cta;" ::: "memory");
        const int pre = niter < NSTAGE ? niter : NSTAGE;
        for (int s = 0; s < pre; ++s) {
            const int kr = r0 + 2 * s;
            const uint32_t bytes = (uint32_t)min(r1 - kr, 2) * ROW_BYTES;
            const uint32_t mb = smem_u32(&mbar[s]);
            mbar_expect_tx(mb, bytes);
            bulk_g2s(smem_u32(&stg[(size_t)s * STAGE_ROWS * ROW_F4]),
                     W + (size_t)kr * D, bytes, mb);
        }
    }
    __syncthreads();

    int s = 0;            // stage index (avoids % in loop)
    uint32_t ph = 0;      // stage parity
    for (int i = 0; i < niter; ++i) {
        mbar_wait(smem_u32(&mbar[s]), ph);

        const int jA = r0 + 2 * i;
        const int j  = jA + grp;
        const int p2 = i & 1;
        if (j < r1) {
            const float4* __restrict__ wrow = &stg[((size_t)s * STAGE_ROWS + grp) * ROW_F4];
            float a0 = 0.0f, a1 = 0.0f;
#pragma unroll
            for (int q = 0; q < 8; ++q) {
                const float4 w = wrow[q * 128 + gtid];
                a0 += w.x * xa[q].x + w.y * xa[q].y + w.z * xa[q].z + w.w * xa[q].w;
                a1 += w.x * xb[q].x + w.y * xb[q].y + w.z * xb[q].z + w.w * xb[q].w;
            }
#pragma unroll
            for (int off = 16; off; off >>= 1) {
                a0 += __shfl_xor_sync(0xFFFFFFFFu, a0, off);
                a1 += __shfl_xor_sync(0xFFFFFFFFu, a1, off);
            }
            if (lane == 0) { red[p2][grp][0][wig] = a0; red[p2][grp][1][wig] = a1; }
        }
        __syncthreads();   // stage fully consumed; partials visible

        // Refill this stage immediately (keep the DMA queue deep).
        if (tid == 0) {
            const int ipre = i + NSTAGE;
            if (ipre < niter) {
                const int kr = r0 + 2 * ipre;
                const uint32_t bytes = (uint32_t)min(r1 - kr, 2) * ROW_BYTES;
                const uint32_t mb = smem_u32(&mbar[s]);
                mbar_expect_tx(mb, bytes);
                bulk_g2s(smem_u32(&stg[(size_t)s * STAGE_ROWS * ROW_F4]),
                         W + (size_t)kr * D, bytes, mb);
            }
        }
        // Epilogue for the two rows (threads 0 and 1; race-free via p2 slots).
        if (tid < 2) {
            const int jj = jA + tid;
            if (jj < r1) {
                float s0 = red[p2][tid][0][0] + red[p2][tid][0][1]
                         + red[p2][tid][0][2] + red[p2][tid][0][3];
                float s1 = red[p2][tid][1][0] + red[p2][tid][1][1]
                         + red[p2][tid][1][2] + red[p2][tid][1][3];
                const float bb = b ? b[jj] : 0.0f;
                s0 += bb; s1 += bb;
                if (RESID) { s0 += resid[jj]; s1 += resid[N + jj]; }
                if (RELU)  { s0 = fmaxf(s0, 0.0f); s1 = fmaxf(s1, 0.0f); }
                out[jj]     = s0;
                out[N + jj] = s1;
            }
        }

        if (++s == NSTAGE) { s = 0; ph ^= 1; }
    }
}

// ---------------------------------------------------------------------------
// Stage 2: multi-head attention on the 2-token sequence (tiny; one block).
// ---------------------------------------------------------------------------
__global__ void k_attn() {
    __shared__ float s_scores[8];
    __shared__ float s_attn[8];
    const int tid = threadIdx.x;
    const int warp = tid >> 5, lane = tid & 31;

    const int h = warp >> 2, l = (warp >> 1) & 1, m = warp & 1;
    const float* __restrict__ q = g_qkv + l * 3 * D + h * HD;
    const float* __restrict__ k = g_qkv + m * 3 * D + D + h * HD;
    float acc = 0.0f;
#pragma unroll 4
    for (int i = lane; i < HD; i += 32) acc += q[i] * k[i];
#pragma unroll
    for (int off = 16; off; off >>= 1) acc += __shfl_xor_sync(0xFFFFFFFFu, acc, off);
    if (lane == 0) s_scores[warp] = acc * rsqrtf((float)HD);
    __syncthreads();

    if (tid < 4) {
        int hh = tid >> 1, ll = tid & 1;
        float s0v = s_scores[hh * 4 + ll * 2 + 0];
        float s1v = s_scores[hh * 4 + ll * 2 + 1];
        float mx = fmaxf(s0v, s1v);
        float e0 = __expf(s0v - mx), e1 = __expf(s1v - mx);
        float inv = 1.0f / (e0 + e1);
        s_attn[hh * 4 + ll * 2 + 0] = e0 * inv;
        s_attn[hh * 4 + ll * 2 + 1] = e1 * inv;
    }
    __syncthreads();

    for (int i = tid; i < 2 * D; i += blockDim.x) {
        int l2 = i / D;
        int d = i - l2 * D;
        int h2 = d / HD;
        float v0 = g_qkv[0 * 3 * D + 2 * D + d];
        float v1 = g_qkv[1 * 3 * D + 2 * D + d];
        g_o[i] = s_attn[h2 * 4 + l2 * 2 + 0] * v0 +
                 s_attn[h2 * 4 + l2 * 2 + 1] * v1;
    }
}

// ---------------------------------------------------------------------------
// Stage 7: out = 0.5 * dot(g0 + g1, exp_w2) + exp_b2
// ---------------------------------------------------------------------------
__global__ void k_final(const float* __restrict__ w2,
                        const float* __restrict__ b2,
                        float* __restrict__ out) {
    __shared__ float red[32];
    float acc = 0.0f;
    for (int i = threadIdx.x; i < E; i += blockDim.x)
        acc += (g_g[i] + g_g[E + i]) * w2[i];
#pragma unroll
    for (int off = 16; off; off >>= 1) acc += __shfl_xor_sync(0xFFFFFFFFu, acc, off);
    const int warp = threadIdx.x >> 5, lane = threadIdx.x & 31;
    if (lane == 0) red[warp] = acc;
    __syncthreads();
    if (threadIdx.x == 0) {
        float s = 0.0f;
        const int nw = blockDim.x >> 5;
        for (int w = 0; w < nw; ++w) s += red[w];
        out[0] = 0.5f * s + b2[0];
    }
}

// ---------------------------------------------------------------------------
extern "C" void kernel_launch(void* const* d_in, const int* in_sizes, int n_in,
                              void* d_out, int out_size) {
    const float* ray        = (const float*)d_in[0];
    const float* emb1_w     = (const float*)d_in[1];
    const float* emb1_b     = (const float*)d_in[2];
    const float* emb2_w     = (const float*)d_in[3];
    const float* emb2_b     = (const float*)d_in[4];
    const float* attn_in_w  = (const float*)d_in[5];
    const float* attn_in_b  = (const float*)d_in[6];
    const float* attn_out_w = (const float*)d_in[7];
    const float* attn_out_b = (const float*)d_in[8];
    const float* ffn1_w     = (const float*)d_in[9];
    const float* ffn1_b     = (const float*)d_in[10];
    const float* ffn2_w     = (const float*)d_in[11];
    const float* ffn2_b     = (const float*)d_in[12];
    const float* exp_w1     = (const float*)d_in[13];
    const float* exp_b1     = (const float*)d_in[14];
    const float* exp_w2     = (const float*)d_in[15];
    const float* exp_b2     = (const float*)d_in[16];
    float* out = (float*)d_out;

    float *px, *pqkv, *po, *px1, *ph, *px2, *pg;
    cudaGetSymbolAddress((void**)&px,   g_x);
    cudaGetSymbolAddress((void**)&pqkv, g_qkv);
    cudaGetSymbolAddress((void**)&po,   g_o);
    cudaGetSymbolAddress((void**)&px1,  g_x1);
    cudaGetSymbolAddress((void**)&ph,   g_h);
    cudaGetSymbolAddress((void**)&px2,  g_x2);
    cudaGetSymbolAddress((void**)&pg,   g_g);

    // Unconditional (idempotent, cheap; no static guards allowed).
    cudaFuncSetAttribute(k_gemv_bulk2<false, false>,
                         cudaFuncAttributeMaxDynamicSharedMemorySize, DYN_SMEM);
    cudaFuncSetAttribute(k_gemv_bulk2<false, true>,
                         cudaFuncAttributeMaxDynamicSharedMemorySize, DYN_SMEM);
    cudaFuncSetAttribute(k_gemv_bulk2<true, false>,
                         cudaFuncAttributeMaxDynamicSharedMemorySize, DYN_SMEM);

    const int GRID = 148;   // persistent, 1 block/SM (192 KB smem ring)

    // 0: embeddings -> g_x [2][D]
    k_embed<<<(D + 255) / 256, 256>>>(ray, emb1_w, emb1_b, emb2_w, emb2_b);

    // 1: qkv = x @ attn_in_w^T + b  (201 MB)
    k_gemv_bulk2<false, false><<<GRID, 256, DYN_SMEM>>>(attn_in_w, attn_in_b, px, nullptr, pqkv, 3 * D);

    // 2: attention -> g_o
    k_attn<<<1, 256>>>();

    // 3: x1 = x + o @ attn_out_w^T + b   (67 MB)
    k_gemv_bulk2<false, true><<<GRID, 256, DYN_SMEM>>>(attn_out_w, attn_out_b, po, px, px1, D);

    // 4: h = relu(x1 @ ffn1_w^T + b1)    (67 MB)
    k_gemv_bulk2<true, false><<<GRID, 256, DYN_SMEM>>>(ffn1_w, ffn1_b, px1, nullptr, ph, D);

    // 5: x2 = x1 + h @ ffn2_w^T + b2     (67 MB)
    k_gemv_bulk2<false, true><<<GRID, 256, DYN_SMEM>>>(ffn2_w, ffn2_b, ph, px1, px2, D);

    // 6: g = relu(x2 @ exp_w1^T + b1)    (134 MB)
    k_gemv_bulk2<true, false><<<GRID, 256, DYN_SMEM>>>(exp_w1, exp_b1, px2, nullptr, pg, E);

    // 7: out = mean over seq
    k_final<<<1, 1024>>>(exp_w2, exp_b2, out);
}